// round 2
// baseline (speedup 1.0000x reference)
#include <cuda_runtime.h>

// 3D Haar DWT, level 1, zero-pad (exact pairwise) on x [B=2, C=32, D=64, H=128, W=128] f32.
// Output [B, 8C=256, D/2=32, H/2=64, W/2=64], subband order (depth,height,width bits):
// aaa, aad, ada, add, daa, dad, dda, ddd ; channel = sb*C + c.
//
// One thread processes TWO adjacent 2x2x2 cubes along W:
//   loads 4x float4 (rows (2dz,2dy),(2dz,2dy+1),(2dz+1,2dy),(2dz+1,2dy+1))
//   writes 8x float2 (one per subband).
// Pure streaming: 512 MB total traffic, HBM-bound.

#define B_   2
#define C_   32
#define D_   64
#define H_   128
#define W_   128
#define DH   (D_/2)
#define HH   (H_/2)
#define WH   (W_/2)
#define WQ   (W_/4)   // thread handles 2 output-w positions (4 input w)

__global__ void __launch_bounds__(256) haar3d_kernel(
    const float* __restrict__ x, float* __restrict__ out)
{
    const float K = 0.35355339059327373f;  // (1/sqrt(2))^3

    int t = blockIdx.x * blockDim.x + threadIdx.x;
    // decompose: t = ((((b*C + c)*DH + dz)*HH + dy)*WQ + wq)
    int wq =  t        & (WQ - 1);         // 0..31
    int dy = (t >> 5)  & (HH - 1);         // 0..63
    int dz = (t >> 11) & (DH - 1);         // 0..31
    int c  = (t >> 16) & (C_ - 1);         // 0..31
    int b  =  t >> 21;                     // 0..1

    // ---- input loads: 4 rows x float4 ----
    size_t ibase = ((((size_t)(b * C_ + c) * D_ + 2 * dz) * H_ + 2 * dy) * W_) + 4 * wq;
    const float4 r00 = *(const float4*)(x + ibase);                         // d=0, h=0
    const float4 r01 = *(const float4*)(x + ibase + W_);                    // d=0, h=1
    const float4 r10 = *(const float4*)(x + ibase + (size_t)H_ * W_);       // d=1, h=0
    const float4 r11 = *(const float4*)(x + ibase + (size_t)H_ * W_ + W_);  // d=1, h=1

    // ---- butterfly: width pairs first (per row), two cubes p=0 (.x,.y) p=1 (.z,.w) ----
    // width stage
    float wl00a = r00.x + r00.y, wh00a = r00.x - r00.y;  // cube 0
    float wl01a = r01.x + r01.y, wh01a = r01.x - r01.y;
    float wl10a = r10.x + r10.y, wh10a = r10.x - r10.y;
    float wl11a = r11.x + r11.y, wh11a = r11.x - r11.y;

    float wl00b = r00.z + r00.w, wh00b = r00.z - r00.w;  // cube 1
    float wl01b = r01.z + r01.w, wh01b = r01.z - r01.w;
    float wl10b = r10.z + r10.w, wh10b = r10.z - r10.w;
    float wl11b = r11.z + r11.w, wh11b = r11.z - r11.w;

    // height stage (combine h=0,h=1 within each depth), then depth stage.
    // subband sb = 4*depth_hp + 2*height_hp + 1*width_hp
    float s0[8], s1[8];
    {
        // cube 0
        float hl_l0 = wl00a + wl01a, hh_l0 = wl00a - wl01a;  // depth 0, width-low
        float hl_h0 = wh00a + wh01a, hh_h0 = wh00a - wh01a;  // depth 0, width-high
        float hl_l1 = wl10a + wl11a, hh_l1 = wl10a - wl11a;  // depth 1
        float hl_h1 = wh10a + wh11a, hh_h1 = wh10a - wh11a;
        s0[0] = (hl_l0 + hl_l1) * K;  // aaa
        s0[1] = (hl_h0 + hl_h1) * K;  // aad
        s0[2] = (hh_l0 + hh_l1) * K;  // ada
        s0[3] = (hh_h0 + hh_h1) * K;  // add
        s0[4] = (hl_l0 - hl_l1) * K;  // daa
        s0[5] = (hl_h0 - hl_h1) * K;  // dad
        s0[6] = (hh_l0 - hh_l1) * K;  // dda
        s0[7] = (hh_h0 - hh_h1) * K;  // ddd
    }
    {
        // cube 1
        float hl_l0 = wl00b + wl01b, hh_l0 = wl00b - wl01b;
        float hl_h0 = wh00b + wh01b, hh_h0 = wh00b - wh01b;
        float hl_l1 = wl10b + wl11b, hh_l1 = wl10b - wl11b;
        float hl_h1 = wh10b + wh11b, hh_h1 = wh10b - wh11b;
        s1[0] = (hl_l0 + hl_l1) * K;
        s1[1] = (hl_h0 + hl_h1) * K;
        s1[2] = (hh_l0 + hh_l1) * K;
        s1[3] = (hh_h0 + hh_h1) * K;
        s1[4] = (hl_l0 - hl_l1) * K;
        s1[5] = (hl_h0 - hl_h1) * K;
        s1[6] = (hh_l0 - hh_l1) * K;
        s1[7] = (hh_h0 - hh_h1) * K;
    }

    // ---- output: channel = sb*C + c ; float2 per subband ----
    size_t obase = ((((size_t)(b * 8 * C_ + c) * DH + dz) * HH + dy) * WH) + 2 * wq;
    const size_t sbStride = (size_t)C_ * DH * HH * WH;  // sb advances 32 channels

#pragma unroll
    for (int sb = 0; sb < 8; sb++) {
        *(float2*)(out + obase + (size_t)sb * sbStride) = make_float2(s0[sb], s1[sb]);
    }
}

extern "C" void kernel_launch(void* const* d_in, const int* in_sizes, int n_in,
                              void* d_out, int out_size) {
    const float* x = (const float*)d_in[0];
    float* out = (float*)d_out;
    // total threads = B*C*DH*HH*WQ = 2*32*32*64*32 = 4,194,304
    const int total = B_ * C_ * DH * HH * WQ;
    haar3d_kernel<<<total / 256, 256>>>(x, out);
}

// round 3
// speedup vs baseline: 1.0016x; 1.0016x over previous
#include <cuda_runtime.h>

// 3D Haar DWT, level 1, x [B=2, C=32, D=64, H=128, W=128] f32
// -> out [B, 8C, D/2, H/2, W/2], subband order aaa,aad,ada,add,daa,dad,dda,ddd
// (bits: depth,height,width; channel = sb*C + c).
//
// R2: 4 output-w per thread. 8 front-batched LDG.128 (MLP=8), 8 STG.128
// (one float4 per subband stream, 512B contiguous per warp per stream),
// streaming stores (__stcs). Pure 512 MB stream, HBM-bound.

#define B_   2
#define C_   32
#define D_   64
#define H_   128
#define W_   128
#define DH   (D_/2)
#define HH   (H_/2)
#define WH   (W_/2)
#define WO8  (W_/8)   // thread handles 4 output-w positions (8 input w)

// haar cube butterfly for one 2x2x2 cube: inputs (x000,x001,x010,x011,x100,x101,x110,x111)
// indices = (d,h,w). Writes the 8 subbands * K into s[8] (sb = 4d|2h|1w high-pass bits).
__device__ __forceinline__ void haar_cube(
    float x000, float x001, float x010, float x011,
    float x100, float x101, float x110, float x111,
    float* __restrict__ s)
{
    const float K = 0.35355339059327373f;  // (1/sqrt2)^3
    // width stage
    float wl0 = x000 + x001, wh0 = x000 - x001;  // d0 h0
    float wl1 = x010 + x011, wh1 = x010 - x011;  // d0 h1
    float wl2 = x100 + x101, wh2 = x100 - x101;  // d1 h0
    float wl3 = x110 + x111, wh3 = x110 - x111;  // d1 h1
    // height stage
    float hl_l0 = wl0 + wl1, hh_l0 = wl0 - wl1;  // d0
    float hl_h0 = wh0 + wh1, hh_h0 = wh0 - wh1;
    float hl_l1 = wl2 + wl3, hh_l1 = wl2 - wl3;  // d1
    float hl_h1 = wh2 + wh3, hh_h1 = wh2 - wh3;
    // depth stage + scale
    s[0] = (hl_l0 + hl_l1) * K;
    s[1] = (hl_h0 + hl_h1) * K;
    s[2] = (hh_l0 + hh_l1) * K;
    s[3] = (hh_h0 + hh_h1) * K;
    s[4] = (hl_l0 - hl_l1) * K;
    s[5] = (hl_h0 - hl_h1) * K;
    s[6] = (hh_l0 - hh_l1) * K;
    s[7] = (hh_h0 - hh_h1) * K;
}

__global__ void __launch_bounds__(256) haar3d_kernel(
    const float* __restrict__ x, float* __restrict__ out)
{
    int t = blockIdx.x * blockDim.x + threadIdx.x;
    // t = ((((b*C + c)*DH + dz)*HH + dy)*WO8 + wq)
    int wq =  t        & (WO8 - 1);        // 0..15
    int dy = (t >> 4)  & (HH - 1);         // 0..63
    int dz = (t >> 10) & (DH - 1);         // 0..31
    int c  = (t >> 15) & (C_ - 1);         // 0..31
    int b  =  t >> 20;                     // 0..1

    // ---- 8 front-batched LDG.128: 4 rows x 2 groups (w offsets +0, +4) ----
    size_t ibase = ((((size_t)(b * C_ + c) * D_ + 2 * dz) * H_ + 2 * dy) * W_) + 8 * wq;
    const size_t HW = (size_t)H_ * W_;
    const float4 a00 = *(const float4*)(x + ibase);              // d0 h0 g0
    const float4 b00 = *(const float4*)(x + ibase + 4);          // d0 h0 g1
    const float4 a01 = *(const float4*)(x + ibase + W_);         // d0 h1 g0
    const float4 b01 = *(const float4*)(x + ibase + W_ + 4);     // d0 h1 g1
    const float4 a10 = *(const float4*)(x + ibase + HW);         // d1 h0 g0
    const float4 b10 = *(const float4*)(x + ibase + HW + 4);     // d1 h0 g1
    const float4 a11 = *(const float4*)(x + ibase + HW + W_);    // d1 h1 g0
    const float4 b11 = *(const float4*)(x + ibase + HW + W_ + 4);// d1 h1 g1

    // ---- 4 cubes: group0 (.x,.y)/(.z,.w), group1 (.x,.y)/(.z,.w) ----
    float s0[8], s1[8], s2[8], s3[8];
    haar_cube(a00.x, a00.y, a01.x, a01.y, a10.x, a10.y, a11.x, a11.y, s0);
    haar_cube(a00.z, a00.w, a01.z, a01.w, a10.z, a10.w, a11.z, a11.w, s1);
    haar_cube(b00.x, b00.y, b01.x, b01.y, b10.x, b10.y, b11.x, b11.y, s2);
    haar_cube(b00.z, b00.w, b01.z, b01.w, b10.z, b10.w, b11.z, b11.w, s3);

    // ---- 8 streaming STG.128, one per subband; out channel = sb*C + c ----
    size_t obase = ((((size_t)(b * 8 * C_ + c) * DH + dz) * HH + dy) * WH) + 4 * wq;
    const size_t sbStride = (size_t)C_ * DH * HH * WH;  // +C_ channels per subband

#pragma unroll
    for (int sb = 0; sb < 8; sb++) {
        float4 v = make_float4(s0[sb], s1[sb], s2[sb], s3[sb]);
        __stcs((float4*)(out + obase + (size_t)sb * sbStride), v);
    }
}

extern "C" void kernel_launch(void* const* d_in, const int* in_sizes, int n_in,
                              void* d_out, int out_size) {
    const float* x = (const float*)d_in[0];
    float* out = (float*)d_out;
    // total threads = B*C*DH*HH*WO8 = 2*32*32*64*16 = 2,097,152
    const int total = B_ * C_ * DH * HH * WO8;
    haar3d_kernel<<<total / 256, 256>>>(x, out);
}

// round 4
// speedup vs baseline: 1.0020x; 1.0004x over previous
#include <cuda_runtime.h>

// 3D Haar DWT, level 1, x [B=2, C=32, D=64, H=128, W=128] f32
// -> out [B, 8C, D/2, H/2, W/2], subband order aaa,aad,ada,add,daa,dad,dda,ddd
// (bits: depth,height,width; channel = sb*C + c).
//
// R2: 4 output-w per thread. 8 front-batched LDG.128 (MLP=8), 8 STG.128
// (one float4 per subband stream, 512B contiguous per warp per stream),
// streaming stores (__stcs). Pure 512 MB stream, HBM-bound.

#define B_   2
#define C_   32
#define D_   64
#define H_   128
#define W_   128
#define DH   (D_/2)
#define HH   (H_/2)
#define WH   (W_/2)
#define WO8  (W_/8)   // thread handles 4 output-w positions (8 input w)

// haar cube butterfly for one 2x2x2 cube: inputs (x000,x001,x010,x011,x100,x101,x110,x111)
// indices = (d,h,w). Writes the 8 subbands * K into s[8] (sb = 4d|2h|1w high-pass bits).
__device__ __forceinline__ void haar_cube(
    float x000, float x001, float x010, float x011,
    float x100, float x101, float x110, float x111,
    float* __restrict__ s)
{
    const float K = 0.35355339059327373f;  // (1/sqrt2)^3
    // width stage
    float wl0 = x000 + x001, wh0 = x000 - x001;  // d0 h0
    float wl1 = x010 + x011, wh1 = x010 - x011;  // d0 h1
    float wl2 = x100 + x101, wh2 = x100 - x101;  // d1 h0
    float wl3 = x110 + x111, wh3 = x110 - x111;  // d1 h1
    // height stage
    float hl_l0 = wl0 + wl1, hh_l0 = wl0 - wl1;  // d0
    float hl_h0 = wh0 + wh1, hh_h0 = wh0 - wh1;
    float hl_l1 = wl2 + wl3, hh_l1 = wl2 - wl3;  // d1
    float hl_h1 = wh2 + wh3, hh_h1 = wh2 - wh3;
    // depth stage + scale
    s[0] = (hl_l0 + hl_l1) * K;
    s[1] = (hl_h0 + hl_h1) * K;
    s[2] = (hh_l0 + hh_l1) * K;
    s[3] = (hh_h0 + hh_h1) * K;
    s[4] = (hl_l0 - hl_l1) * K;
    s[5] = (hl_h0 - hl_h1) * K;
    s[6] = (hh_l0 - hh_l1) * K;
    s[7] = (hh_h0 - hh_h1) * K;
}

__global__ void __launch_bounds__(256) haar3d_kernel(
    const float* __restrict__ x, float* __restrict__ out)
{
    int t = blockIdx.x * blockDim.x + threadIdx.x;
    // t = ((((b*C + c)*DH + dz)*HH + dy)*WO8 + wq)
    int wq =  t        & (WO8 - 1);        // 0..15
    int dy = (t >> 4)  & (HH - 1);         // 0..63
    int dz = (t >> 10) & (DH - 1);         // 0..31
    int c  = (t >> 15) & (C_ - 1);         // 0..31
    int b  =  t >> 20;                     // 0..1

    // ---- 8 front-batched LDG.128: 4 rows x 2 groups (w offsets +0, +4) ----
    size_t ibase = ((((size_t)(b * C_ + c) * D_ + 2 * dz) * H_ + 2 * dy) * W_) + 8 * wq;
    const size_t HW = (size_t)H_ * W_;
    const float4 a00 = *(const float4*)(x + ibase);              // d0 h0 g0
    const float4 b00 = *(const float4*)(x + ibase + 4);          // d0 h0 g1
    const float4 a01 = *(const float4*)(x + ibase + W_);         // d0 h1 g0
    const float4 b01 = *(const float4*)(x + ibase + W_ + 4);     // d0 h1 g1
    const float4 a10 = *(const float4*)(x + ibase + HW);         // d1 h0 g0
    const float4 b10 = *(const float4*)(x + ibase + HW + 4);     // d1 h0 g1
    const float4 a11 = *(const float4*)(x + ibase + HW + W_);    // d1 h1 g0
    const float4 b11 = *(const float4*)(x + ibase + HW + W_ + 4);// d1 h1 g1

    // ---- 4 cubes: group0 (.x,.y)/(.z,.w), group1 (.x,.y)/(.z,.w) ----
    float s0[8], s1[8], s2[8], s3[8];
    haar_cube(a00.x, a00.y, a01.x, a01.y, a10.x, a10.y, a11.x, a11.y, s0);
    haar_cube(a00.z, a00.w, a01.z, a01.w, a10.z, a10.w, a11.z, a11.w, s1);
    haar_cube(b00.x, b00.y, b01.x, b01.y, b10.x, b10.y, b11.x, b11.y, s2);
    haar_cube(b00.z, b00.w, b01.z, b01.w, b10.z, b10.w, b11.z, b11.w, s3);

    // ---- 8 streaming STG.128, one per subband; out channel = sb*C + c ----
    size_t obase = ((((size_t)(b * 8 * C_ + c) * DH + dz) * HH + dy) * WH) + 4 * wq;
    const size_t sbStride = (size_t)C_ * DH * HH * WH;  // +C_ channels per subband

#pragma unroll
    for (int sb = 0; sb < 8; sb++) {
        float4 v = make_float4(s0[sb], s1[sb], s2[sb], s3[sb]);
        __stcs((float4*)(out + obase + (size_t)sb * sbStride), v);
    }
}

extern "C" void kernel_launch(void* const* d_in, const int* in_sizes, int n_in,
                              void* d_out, int out_size) {
    const float* x = (const float*)d_in[0];
    float* out = (float*)d_out;
    // total threads = B*C*DH*HH*WO8 = 2*32*32*64*16 = 2,097,152
    const int total = B_ * C_ * DH * HH * WO8;
    haar3d_kernel<<<total / 256, 256>>>(x, out);
}